// round 12
// baseline (speedup 1.0000x reference)
#include <cuda_runtime.h>
#include <cuda_bf16.h>
#include <math.h>
#include <stdint.h>

#define MNODES 4096
#define NLEV   16
#define NTOT   65536
#define HID    256
#define PRED   16
#define HEADS  4
#define HD     64
#define LAYERS 3
#define NB     61440
#define LN_EPS 1e-5f

// ---------------- device scratch ----------------
__device__ __align__(16) float    g_QZ[(size_t)NB * 512];        // [Qh | q@Wc1^T] fp32
__device__ __align__(16) float    g_KV[2][(size_t)MNODES * 512]; // ping-pong [K|V] fp32
__device__ __align__(16) uint32_t g_Xp[(size_t)NTOT * 256];      // x permuted tf32
__device__ __align__(16) uint32_t g_Hp[(size_t)NB * 256];        // h_l rows 4096.. permuted
__device__ __align__(16) uint32_t g_Hp0[(size_t)MNODES * 256];   // h level-0 rows permuted
__device__ __align__(16) float    g_Wkv[LAYERS * 512 * 256];     // stacked fp32 (staging)
__device__ __align__(16) float    g_bkv[LAYERS * 512];
__device__ __align__(16) float    g_Wqc[LAYERS * 512 * 256];
__device__ __align__(16) float    g_bqc[LAYERS * 512];
__device__ __align__(16) float    g_W2 [LAYERS * 256 * 256];
__device__ __align__(16) float    g_b2 [LAYERS * 256];
__device__ __align__(16) uint32_t g_Wkvp[LAYERS * 512 * 256];    // permuted tf32
__device__ __align__(16) uint32_t g_Wqcp[LAYERS * 512 * 256];
__device__ __align__(16) uint32_t g_W2p [LAYERS * 256 * 256];
__device__ __align__(16) uint32_t g_Winp[256 * 256];

// ---------------- helpers ----------------
__device__ __forceinline__ uint32_t cvt_tf32(float x) {
    uint32_t r; asm("cvt.rna.tf32.f32 %0, %1;" : "=r"(r) : "f"(x)); return r;
}
__device__ __forceinline__ void mma_tf32(float c[4], const uint4& a, const uint2& b) {
    asm volatile(
        "mma.sync.aligned.m16n8k8.row.col.f32.tf32.tf32.f32 "
        "{%0,%1,%2,%3}, {%4,%5,%6,%7}, {%8,%9}, {%0,%1,%2,%3};"
        : "+f"(c[0]), "+f"(c[1]), "+f"(c[2]), "+f"(c[3])
        : "r"(a.x), "r"(a.y), "r"(a.z), "r"(a.w), "r"(b.x), "r"(b.y));
}
// permuted A layout (u32 index) for element (row, k), K=256 total
__device__ __forceinline__ int pidx(int row, int k, int mgTot) {
    int kc = k >> 5, ks = (k >> 3) & 3;
    return ((kc * mgTot + (row >> 4)) * 4 + ks) * 128
         + (row & 7) * 16 + (k & 3) * 4 + ((row >> 3) & 1) + 2 * ((k >> 2) & 1);
}
// permuted B layout (u32 index) for element (n, k)
__device__ __forceinline__ int bidx(int n, int k, int ngTot) {
    int kc = k >> 5, ks = (k >> 3) & 3;
    return (((kc * ngTot + (n >> 3)) * 4 + ks) * 32 + (n & 7) * 4 + (k & 3)) * 2
         + ((k >> 2) & 1);
}

// ---------------- weight prep ----------------
__global__ void prep_stack(const float* __restrict__ Wq, const float* __restrict__ bq,
                           const float* __restrict__ Wc,
                           const float* __restrict__ Wk, const float* __restrict__ bk,
                           const float* __restrict__ Wv, const float* __restrict__ bv)
{
    int r = blockIdx.x, which = blockIdx.y, l = blockIdx.z, t = threadIdx.x;
    if (which == 0) {
        if (r < 256) {
            g_Wkv[((size_t)l*512 + r)*256 + t] = Wk[((size_t)l*256 + r)*256 + t];
            if (t == 0) g_bkv[l*512 + r] = bk[l*256 + r];
        } else {
            g_Wkv[((size_t)l*512 + r)*256 + t] = Wv[((size_t)l*256 + r-256)*256 + t];
            if (t == 0) g_bkv[l*512 + r] = bv[l*256 + r-256];
        }
    } else {
        if (r < 256) {
            g_Wqc[((size_t)l*512 + r)*256 + t] = Wq[((size_t)l*256 + r)*256 + t];
            if (t == 0) g_bqc[l*512 + r] = bq[l*256 + r];
        } else {
            g_Wqc[((size_t)l*512 + r)*256 + t] = Wc[((size_t)l*256 + (r-256))*512 + t];
            if (t == 0) g_bqc[l*512 + r] = 0.f;
        }
    }
}
__global__ void prep_fold(const float* __restrict__ Wc, const float* __restrict__ Wo)
{
    int l = blockIdx.z;
    int o = blockIdx.y * 16 + threadIdx.y;
    int i = blockIdx.x * 16 + threadIdx.x;
    const float* wc2 = Wc + ((size_t)l*256 + o)*512 + 256;
    float acc = 0.f;
    for (int j = 0; j < 256; j++)
        acc += wc2[j] * Wo[((size_t)l*256 + j)*256 + i];
    g_W2[((size_t)l*256 + o)*256 + i] = acc;
}
__global__ void prep_b2(const float* __restrict__ Wc, const float* __restrict__ bo,
                        const float* __restrict__ bc)
{
    int l = blockIdx.x, o = threadIdx.x;
    const float* wc2 = Wc + ((size_t)l*256 + o)*512 + 256;
    float acc = bc[l*256 + o];
    for (int j = 0; j < 256; j++)
        acc += wc2[j] * bo[l*256 + j];
    g_b2[l*256 + o] = acc;
}
// permute a [N,256] fp32 row-major weight into tf32 fragment order
__global__ void permW(const float* __restrict__ src, uint32_t* __restrict__ dst,
                      int N, int ngTot, int srcStride, int dstStride)
{
    int l = blockIdx.y;
    int idx = blockIdx.x * 256 + threadIdx.x;
    if (idx >= N * 256) return;
    int n = idx >> 8, k = idx & 255;
    dst[(size_t)l * dstStride + bidx(n, k, ngTot)] =
        cvt_tf32(src[(size_t)l * srcStride + (size_t)n * 256 + k]);
}
// permute activations [M,256] fp32 into tf32 fragment order
__global__ void permX(const float* __restrict__ src, uint32_t* __restrict__ dst, int mgTot)
{
    int idx = blockIdx.x * 256 + threadIdx.x;
    int row = idx >> 8, k = idx & 255;
    dst[pidx(row, k, mgTot)] = cvt_tf32(src[(size_t)row * 256 + k]);
}

// =====================================================================
// GEMM on pre-permuted operands: C[M,N] = A @ B^T + bias
// BM=128, BN=64, 256 thr (8 warps, 4M x 2N). Smem staging = plain uint4 copies.
// Optional permuted-A outputs (row<4096 -> P0, else P1).
// =====================================================================
__global__ __launch_bounds__(256)
void gemm_perm(const uint32_t* __restrict__ Ap, int mgTot,
               const uint32_t* __restrict__ Bp, int ngTot,
               const float* __restrict__ bias,
               float* __restrict__ C, int ldc,
               uint32_t* __restrict__ P0, uint32_t* __restrict__ P1)
{
    __shared__ uint32_t As[2][4096];
    __shared__ uint32_t Bs[2][2048];
    const int t = threadIdx.x, lane = t & 31, warp = t >> 5;
    const int warpN = warp & 1, warpM = warp >> 1;
    const int gid = lane >> 2, tig = lane & 3;
    const int bm = blockIdx.y * 128, bn = blockIdx.x * 64;
    const int mg0 = bm >> 4, ng0 = bn >> 3;

    float acc[2][4][4];
    #pragma unroll
    for (int i = 0; i < 2; i++)
        #pragma unroll
        for (int j = 0; j < 4; j++)
            #pragma unroll
            for (int q = 0; q < 4; q++) acc[i][j][q] = 0.f;

    uint4 aR[4], bR[2];
    auto loadG = [&](int kc) {
        #pragma unroll
        for (int i = 0; i < 4; i++) {
            int idx = t + i * 256;
            int mgl = idx >> 7, r = idx & 127;
            aR[i] = ((const uint4*)Ap)[(size_t)(kc * mgTot + mg0 + mgl) * 128 + r];
        }
        #pragma unroll
        for (int i = 0; i < 2; i++) {
            int idx = t + i * 256;
            int ngl = idx >> 6, r = idx & 63;
            bR[i] = ((const uint4*)Bp)[(size_t)(kc * ngTot + ng0 + ngl) * 64 + r];
        }
    };
    auto storeS = [&](int buf) {
        #pragma unroll
        for (int i = 0; i < 4; i++) ((uint4*)As[buf])[t + i * 256] = aR[i];
        #pragma unroll
        for (int i = 0; i < 2; i++) ((uint4*)Bs[buf])[t + i * 256] = bR[i];
    };
    auto compute = [&](int buf) {
        #pragma unroll
        for (int ks = 0; ks < 4; ks++) {
            uint4 a[2]; uint2 b[4];
            #pragma unroll
            for (int mf = 0; mf < 2; mf++)
                a[mf] = ((const uint4*)As[buf])[((warpM * 2 + mf) * 4 + ks) * 32 + lane];
            #pragma unroll
            for (int nf = 0; nf < 4; nf++)
                b[nf] = ((const uint2*)Bs[buf])[((warpN * 4 + nf) * 4 + ks) * 32 + lane];
            #pragma unroll
            for (int mf = 0; mf < 2; mf++)
                #pragma unroll
                for (int nf = 0; nf < 4; nf++)
                    mma_tf32(acc[mf][nf], a[mf], b[nf]);
        }
    };

    loadG(0); storeS(0); __syncthreads();
    #pragma unroll 1
    for (int kc = 0; kc < 8; kc++) {
        int cur = kc & 1;
        if (kc < 7) loadG(kc + 1);
        compute(cur);
        if (kc < 7) { storeS(1 - cur); __syncthreads(); }
    }

    #pragma unroll
    for (int mf = 0; mf < 2; mf++) {
        int r0 = bm + warpM * 32 + mf * 16 + gid;
        #pragma unroll
        for (int nf = 0; nf < 4; nf++) {
            int c0 = bn + warpN * 32 + nf * 8 + tig * 2;
            float bx = bias ? bias[c0] : 0.f, by = bias ? bias[c0 + 1] : 0.f;
            float v00 = acc[mf][nf][0] + bx, v01 = acc[mf][nf][1] + by;
            float v10 = acc[mf][nf][2] + bx, v11 = acc[mf][nf][3] + by;
            *(float2*)(C + (size_t)r0 * ldc + c0)       = make_float2(v00, v01);
            *(float2*)(C + (size_t)(r0 + 8) * ldc + c0) = make_float2(v10, v11);
            if (P0) {
                uint32_t* P = (r0 < 4096) ? P0 : P1;
                int rr   = (r0 < 4096) ? r0 : r0 - 4096;
                int mgT  = (r0 < 4096) ? 256 : 3840;
                int base = pidx(rr, c0, mgT);
                P[base]     = cvt_tf32(v00);
                P[base + 4] = cvt_tf32(v01);
                P[base + 1] = cvt_tf32(v10);
                P[base + 5] = cvt_tf32(v11);
            }
        }
    }
}

// =====================================================================
// Fused per-level kernel: attention + zGEMM(+Zq,LN,GELU) + KV projection.
// 256 blocks x 256 thr; block handles 16 nodes of level lv+1.
// =====================================================================
__global__ __launch_bounds__(256)
void fused_level(const int* __restrict__ preds,     // + lv*4096*16
                 int lvbase,                         // lv*4096
                 const float* __restrict__ KVsrc,
                 float* __restrict__ KVdst,
                 const float* __restrict__ QZrow,    // g_QZ + lv*4096*512
                 const uint32_t* __restrict__ W2p,
                 const float* __restrict__ b2,
                 const uint32_t* __restrict__ Wkvp,
                 const float* __restrict__ bkv,
                 const float* __restrict__ gma, const float* __restrict__ bta,
                 float* __restrict__ outp,           // + (lv+1)*4096*1024 + (l+1)*256
                 uint32_t* __restrict__ Hp)          // g_Hp or null
{
    __shared__ int   sp[16][16];
    __shared__ float qs[16][256];
    __shared__ float sattn[16][68];
    __shared__ float redA[16][8], redB[16][8];
    extern __shared__ uint32_t Az[];                 // 4096 u32 = 16KB

    const int t = threadIdx.x, lane = t & 31, warp = t >> 5;
    const int gid = lane >> 2, tig = lane & 3;
    const int m0 = blockIdx.x * 16;

    // ---- load preds + q rows ----
    sp[t >> 4][t & 15] = preds[m0 * 16 + t] - lvbase;
    for (int i = t; i < 1024; i += 256) {
        int m = i >> 6, c4 = i & 63;
        ((float4*)qs[m])[c4] = *(const float4*)(QZrow + (size_t)(m0 + m) * 512 + c4 * 4);
    }
    __syncthreads();

    // ---- phase A: attention (warp per node, 2 nodes/warp) ----
    const int p = lane >> 1, half = lane & 1;
    const int hlo = lane >> 4, hhi = 2 + hlo;    // heads for V float4 slices
    for (int it = 0; it < 2; it++) {
        int m = warp + it * 8;
        const float4* kv = (const float4*)(KVsrc + (size_t)sp[m][p] * 512 + half * 128);
        const float4* q4 = (const float4*)&qs[m][half * 128];
        float s0 = 0.f, s1 = 0.f;
        #pragma unroll
        for (int j = 0; j < 16; j++) {
            float4 k4 = kv[j], qq = q4[j];
            s0 += k4.x*qq.x + k4.y*qq.y + k4.z*qq.z + k4.w*qq.w;
        }
        #pragma unroll
        for (int j = 16; j < 32; j++) {
            float4 k4 = kv[j], qq = q4[j];
            s1 += k4.x*qq.x + k4.y*qq.y + k4.z*qq.z + k4.w*qq.w;
        }
        s0 *= 0.125f; s1 *= 0.125f;
        float m0x = s0, m1x = s1;
        #pragma unroll
        for (int o = 2; o <= 16; o <<= 1) {
            m0x = fmaxf(m0x, __shfl_xor_sync(0xffffffffu, m0x, o));
            m1x = fmaxf(m1x, __shfl_xor_sync(0xffffffffu, m1x, o));
        }
        float e0 = expf(s0 - m0x), e1 = expf(s1 - m1x);
        float t0 = e0, t1 = e1;
        #pragma unroll
        for (int o = 2; o <= 16; o <<= 1) {
            t0 += __shfl_xor_sync(0xffffffffu, t0, o);
            t1 += __shfl_xor_sync(0xffffffffu, t1, o);
        }
        sattn[m][(2*half)*16 + p]   = e0 / t0;
        sattn[m][(2*half+1)*16 + p] = e1 / t1;
        __syncwarp();

        // V aggregation, vectorized: lane owns elems [lane*4, +4) and [128+lane*4, +4)
        float4 alo = make_float4(0.f, 0.f, 0.f, 0.f);
        float4 ahi = make_float4(0.f, 0.f, 0.f, 0.f);
        #pragma unroll
        for (int pp = 0; pp < 16; pp++) {
            const float4* vr = (const float4*)(KVsrc + (size_t)sp[m][pp] * 512 + 256);
            float wl = sattn[m][hlo*16 + pp], wh = sattn[m][hhi*16 + pp];
            float4 v0 = vr[lane];
            float4 v1 = vr[32 + lane];
            alo.x = fmaf(wl, v0.x, alo.x); alo.y = fmaf(wl, v0.y, alo.y);
            alo.z = fmaf(wl, v0.z, alo.z); alo.w = fmaf(wl, v0.w, alo.w);
            ahi.x = fmaf(wh, v1.x, ahi.x); ahi.y = fmaf(wh, v1.y, ahi.y);
            ahi.z = fmaf(wh, v1.z, ahi.z); ahi.w = fmaf(wh, v1.w, ahi.w);
        }
        int b0 = pidx(m, lane * 4, 1);
        Az[b0]      = cvt_tf32(alo.x); Az[b0 + 4]  = cvt_tf32(alo.y);
        Az[b0 + 8]  = cvt_tf32(alo.z); Az[b0 + 12] = cvt_tf32(alo.w);
        int b1 = pidx(m, 128 + lane * 4, 1);
        Az[b1]      = cvt_tf32(ahi.x); Az[b1 + 4]  = cvt_tf32(ahi.y);
        Az[b1 + 8]  = cvt_tf32(ahi.z); Az[b1 + 12] = cvt_tf32(ahi.w);
    }
    __syncthreads();

    // ---- phase B: zGEMM (warp tile 16x32) ----
    float accz[4][4];
    #pragma unroll
    for (int j = 0; j < 4; j++)
        #pragma unroll
        for (int q = 0; q < 4; q++) accz[j][q] = 0.f;

    #pragma unroll 1
    for (int kc = 0; kc < 8; kc++) {
        uint2 bfr[4][4];
        #pragma unroll
        for (int ks = 0; ks < 4; ks++)
            #pragma unroll
            for (int nf = 0; nf < 4; nf++)
                bfr[ks][nf] = ((const uint2*)W2p)[((kc*32 + warp*4 + nf)*4 + ks)*32 + lane];
        #pragma unroll
        for (int ks = 0; ks < 4; ks++) {
            uint4 a = ((const uint4*)Az)[(kc*4 + ks)*32 + lane];
            #pragma unroll
            for (int nf = 0; nf < 4; nf++)
                mma_tf32(accz[nf], a, bfr[ks][nf]);
        }
    }

    // ---- epilogue: +b2+Zq, LN, GELU; write out, Az (perm), Hp (perm) ----
    #pragma unroll
    for (int nf = 0; nf < 4; nf++) {
        int col = warp * 32 + nf * 8 + tig * 2;
        float b0 = b2[col], b1 = b2[col + 1];
        float2 zl = *(const float2*)(QZrow + (size_t)(m0 + gid) * 512 + 256 + col);
        float2 zh = *(const float2*)(QZrow + (size_t)(m0 + gid + 8) * 512 + 256 + col);
        accz[nf][0] += b0 + zl.x;
        accz[nf][1] += b1 + zl.y;
        accz[nf][2] += b0 + zh.x;
        accz[nf][3] += b1 + zh.y;
    }
    #pragma unroll
    for (int rh = 0; rh < 2; rh++) {
        float s1 = 0.f, s2 = 0.f;
        #pragma unroll
        for (int nf = 0; nf < 4; nf++) {
            float z0 = accz[nf][2*rh], z1 = accz[nf][2*rh + 1];
            s1 += z0 + z1;
            s2 += z0*z0 + z1*z1;
        }
        s1 += __shfl_xor_sync(0xffffffffu, s1, 1);
        s2 += __shfl_xor_sync(0xffffffffu, s2, 1);
        s1 += __shfl_xor_sync(0xffffffffu, s1, 2);
        s2 += __shfl_xor_sync(0xffffffffu, s2, 2);
        if (tig == 0) {
            redA[rh * 8 + gid][warp] = s1;
            redB[rh * 8 + gid][warp] = s2;
        }
    }
    __syncthreads();   // also guarantees all warps finished reading Az
    #pragma unroll
    for (int rh = 0; rh < 2; rh++) {
        int rowL = rh * 8 + gid;
        float a = 0.f, b = 0.f;
        #pragma unroll
        for (int w = 0; w < 8; w++) { a += redA[rowL][w]; b += redB[rowL][w]; }
        float mu   = a * (1.f / 256.f);
        float var  = b * (1.f / 256.f) - mu * mu;
        float rstd = rsqrtf(var + LN_EPS);
        #pragma unroll
        for (int nf = 0; nf < 4; nf++) {
            int col = warp * 32 + nf * 8 + tig * 2;
            float z0 = (accz[nf][2*rh]     - mu) * rstd * gma[col]     + bta[col];
            float z1 = (accz[nf][2*rh + 1] - mu) * rstd * gma[col + 1] + bta[col + 1];
            float g0 = 0.5f * z0 * (1.f + erff(z0 * 0.70710678118654752f));
            float g1 = 0.5f * z1 * (1.f + erff(z1 * 0.70710678118654752f));
            ((float2*)(outp + (size_t)(m0 + rowL) * 1024))[col >> 1] =
                make_float2(g0, g1);
            uint32_t c0 = cvt_tf32(g0), c1 = cvt_tf32(g1);
            int base = pidx(rowL, col, 1);
            Az[base] = c0; Az[base + 4] = c1;
            if (Hp) {
                int gb = pidx(lvbase + m0 + rowL, col, 3840);
                Hp[gb] = c0; Hp[gb + 4] = c1;
            }
        }
    }
    __syncthreads();

    // ---- phase C: KV projection (warp tile 16x64) ----
    float acck[8][4];
    #pragma unroll
    for (int j = 0; j < 8; j++)
        #pragma unroll
        for (int q = 0; q < 4; q++) acck[j][q] = 0.f;

    #pragma unroll 1
    for (int kc = 0; kc < 8; kc++) {
        #pragma unroll
        for (int ks = 0; ks < 4; ks++) {
            uint2 bk[8];
            #pragma unroll
            for (int nf = 0; nf < 8; nf++)
                bk[nf] = ((const uint2*)Wkvp)[((kc*64 + warp*8 + nf)*4 + ks)*32 + lane];
            uint4 a = ((const uint4*)Az)[(kc*4 + ks)*32 + lane];
            #pragma unroll
            for (int nf = 0; nf < 8; nf++)
                mma_tf32(acck[nf], a, bk[nf]);
        }
    }
    {
        int r0 = m0 + gid;
        #pragma unroll
        for (int nf = 0; nf < 8; nf++) {
            int col = warp * 64 + nf * 8 + tig * 2;
            float b0 = bkv[col], b1 = bkv[col + 1];
            *(float2*)(KVdst + (size_t)r0 * 512 + col) =
                make_float2(acck[nf][0] + b0, acck[nf][1] + b1);
            *(float2*)(KVdst + (size_t)(r0 + 8) * 512 + col) =
                make_float2(acck[nf][2] + b0, acck[nf][3] + b1);
        }
    }
}

// ---------------- final level-0 copies ----------------
__global__ __launch_bounds__(256)
void copy0(float* __restrict__ out)
{
    int idx = blockIdx.x * 256 + threadIdx.x;   // 4096*256
    int n = idx >> 8, c = idx & 255;
    float v = out[(size_t)n * 1024 + c];
    out[(size_t)n * 1024 + 256 + c] = v;
    out[(size_t)n * 1024 + 512 + c] = v;
    out[(size_t)n * 1024 + 768 + c] = v;
}

// ---------------- host driver ----------------
extern "C" void kernel_launch(void* const* d_in, const int* in_sizes, int n_in,
                              void* d_out, int out_size)
{
    const float* x        = (const float*)d_in[0];
    const int*   preds_lv = (const int*)d_in[3];
    const float* W_in = (const float*)d_in[4];
    const float* b_in = (const float*)d_in[5];
    const float* Wq   = (const float*)d_in[6];
    const float* bq   = (const float*)d_in[7];
    const float* Wk   = (const float*)d_in[8];
    const float* bk   = (const float*)d_in[9];
    const float* Wv   = (const float*)d_in[10];
    const float* bv   = (const float*)d_in[11];
    const float* Wo   = (const float*)d_in[12];
    const float* bo   = (const float*)d_in[13];
    const float* Wc   = (const float*)d_in[14];
    const float* bc   = (const float*)d_in[15];
    const float* ln_g = (const float*)d_in[16];
    const float* ln_b = (const float*)d_in[17];
    float* out = (float*)d_out;

    float *pQZ, *pKV0, *pWkv, *pbkv, *pWqc, *pbqc, *pW2, *pb2;
    uint32_t *pXp, *pHp, *pHp0, *pWkvp, *pWqcp, *pW2p, *pWinp;
    cudaGetSymbolAddress((void**)&pQZ,   g_QZ);
    cudaGetSymbolAddress((void**)&pKV0,  g_KV);
    cudaGetSymbolAddress((void**)&pWkv,  g_Wkv);
    cudaGetSymbolAddress((void**)&pbkv,  g_bkv);
    cudaGetSymbolAddress((void**)&pWqc,  g_Wqc);
    cudaGetSymbolAddress((void**)&pbqc,  g_bqc);
    cudaGetSymbolAddress((void**)&pW2,   g_W2);
    cudaGetSymbolAddress((void**)&pb2,   g_b2);
    cudaGetSymbolAddress((void**)&pXp,   g_Xp);
    cudaGetSymbolAddress((void**)&pHp,   g_Hp);
    cudaGetSymbolAddress((void**)&pHp0,  g_Hp0);
    cudaGetSymbolAddress((void**)&pWkvp, g_Wkvp);
    cudaGetSymbolAddress((void**)&pWqcp, g_Wqcp);
    cudaGetSymbolAddress((void**)&pW2p,  g_W2p);
    cudaGetSymbolAddress((void**)&pWinp, g_Winp);

    // weight prep + permutes
    prep_stack<<<dim3(512, 2, LAYERS), 256>>>(Wq, bq, Wc, Wk, bk, Wv, bv);
    prep_fold<<<dim3(16, 16, LAYERS), dim3(16, 16)>>>(Wc, Wo);
    prep_b2<<<LAYERS, 256>>>(Wc, bo, bc);
    permW<<<dim3(256, 1), 256>>>(W_in, pWinp, 256, 32, 0, 0);
    permW<<<dim3(512, LAYERS), 256>>>(pWqc, pWqcp, 512, 64, 512*256, 512*256);
    permW<<<dim3(512, LAYERS), 256>>>(pWkv, pWkvp, 512, 64, 512*256, 512*256);
    permW<<<dim3(256, LAYERS), 256>>>(pW2,  pW2p,  256, 32, 256*256, 256*256);
    permX<<<NTOT, 256>>>(x, pXp, 4096);

    // h0 = x @ W_in^T + b_in -> out[:,0:256] + permuted copies
    gemm_perm<<<dim3(4, NTOT/128), 256>>>(pXp, 4096, pWinp, 32, b_in,
                                          out, 1024, pHp0, pHp);

    for (int l = 0; l < LAYERS; l++) {
        // [Qh | q@Wc1^T] for all non-source nodes from h_l (permuted in g_Hp)
        gemm_perm<<<dim3(8, NB/128), 256>>>(pHp, 3840,
                                            pWqcp + (size_t)l*512*256, 64,
                                            pbqc + l*512, pQZ, 512,
                                            (uint32_t*)0, (uint32_t*)0);
        // K|V of level 0 (h_l level0 == h0 level0)
        gemm_perm<<<dim3(8, MNODES/128), 256>>>(pHp0, 256,
                                                pWkvp + (size_t)l*512*256, 64,
                                                pbkv + l*512,
                                                pKV0, 512,
                                                (uint32_t*)0, (uint32_t*)0);
        for (int lv = 0; lv < NLEV - 1; lv++) {
            float* KVsrc = pKV0 + (size_t)(lv & 1) * MNODES * 512;
            float* KVdst = pKV0 + (size_t)((lv + 1) & 1) * MNODES * 512;
            fused_level<<<MNODES/16, 256, 16384>>>(
                preds_lv + (size_t)lv * MNODES * 16,
                lv * MNODES,
                KVsrc, KVdst,
                pQZ + (size_t)lv * MNODES * 512,
                pW2p + (size_t)l*256*256, pb2 + l*256,
                pWkvp + (size_t)l*512*256, pbkv + l*512,
                ln_g + l*256, ln_b + l*256,
                out + (size_t)(lv + 1) * MNODES * 1024 + (size_t)(l + 1) * 256,
                (l < LAYERS - 1) ? pHp : (uint32_t*)0);
        }
    }
    copy0<<<4096, 256>>>(out);
}

// round 13
// speedup vs baseline: 1.2691x; 1.2691x over previous
#include <cuda_runtime.h>
#include <cuda_fp16.h>
#include <math.h>
#include <stdint.h>

#define MNODES 4096
#define NLEV   16
#define NTOT   65536
#define HID    256
#define PRED   16
#define HEADS  4
#define HD     64
#define LAYERS 3
#define NB     61440
#define LN_EPS 1e-5f

// ---------------- device scratch ----------------
__device__ __align__(16) float    g_QZ[(size_t)NB * 512];          // [Qh | q@Wc1^T] fp32
__device__ __align__(16) __half   g_KV16[2][(size_t)MNODES * 512]; // ping-pong [K|V] fp16
__device__ __align__(16) uint32_t g_Xp[(size_t)NTOT * 256];        // x permuted tf32
__device__ __align__(16) uint32_t g_Hp[(size_t)NB * 256];          // h_l rows 4096.. permuted tf32
__device__ __align__(16) uint32_t g_Hp0[(size_t)MNODES * 256];     // h level-0 rows permuted tf32
__device__ __align__(16) float    g_Wkv[LAYERS * 512 * 256];       // stacked fp32 (staging)
__device__ __align__(16) float    g_bkv[LAYERS * 512];
__device__ __align__(16) float    g_Wqc[LAYERS * 512 * 256];
__device__ __align__(16) float    g_bqc[LAYERS * 512];
__device__ __align__(16) float    g_W2 [LAYERS * 256 * 256];
__device__ __align__(16) float    g_b2 [LAYERS * 256];
__device__ __align__(16) uint32_t g_Wkvp[LAYERS * 512 * 256];      // tf32 perm (level-0 KV gemm)
__device__ __align__(16) uint32_t g_Wqcp[LAYERS * 512 * 256];      // tf32 perm
__device__ __align__(16) uint32_t g_Winp[256 * 256];               // tf32 perm
__device__ __align__(16) __half   g_W2h [LAYERS * 256 * 256];      // fp16 perm (fused)
__device__ __align__(16) __half   g_Wkvh[LAYERS * 512 * 256];      // fp16 perm (fused)

// ---------------- helpers ----------------
__device__ __forceinline__ uint32_t cvt_tf32(float x) {
    uint32_t r; asm("cvt.rna.tf32.f32 %0, %1;" : "=r"(r) : "f"(x)); return r;
}
__device__ __forceinline__ void mma_tf32(float c[4], const uint4& a, const uint2& b) {
    asm volatile(
        "mma.sync.aligned.m16n8k8.row.col.f32.tf32.tf32.f32 "
        "{%0,%1,%2,%3}, {%4,%5,%6,%7}, {%8,%9}, {%0,%1,%2,%3};"
        : "+f"(c[0]), "+f"(c[1]), "+f"(c[2]), "+f"(c[3])
        : "r"(a.x), "r"(a.y), "r"(a.z), "r"(a.w), "r"(b.x), "r"(b.y));
}
__device__ __forceinline__ void mma_f16(float c[4], const uint4& a, const uint2& b) {
    asm volatile(
        "mma.sync.aligned.m16n8k16.row.col.f32.f16.f16.f32 "
        "{%0,%1,%2,%3}, {%4,%5,%6,%7}, {%8,%9}, {%0,%1,%2,%3};"
        : "+f"(c[0]), "+f"(c[1]), "+f"(c[2]), "+f"(c[3])
        : "r"(a.x), "r"(a.y), "r"(a.z), "r"(a.w), "r"(b.x), "r"(b.y));
}
__device__ __forceinline__ uint32_t f2h2(float a, float b) {
    __half2 h = __floats2half2_rn(a, b); return *(uint32_t*)&h;
}
// tf32 permuted A layout (u32 index) for element (row, k), K=256 total
__device__ __forceinline__ int pidx(int row, int k, int mgTot) {
    int kc = k >> 5, ks = (k >> 3) & 3;
    return ((kc * mgTot + (row >> 4)) * 4 + ks) * 128
         + (row & 7) * 16 + (k & 3) * 4 + ((row >> 3) & 1) + 2 * ((k >> 2) & 1);
}
// tf32 permuted B layout (u32 index) for element (n, k)
__device__ __forceinline__ int bidx(int n, int k, int ngTot) {
    int kc = k >> 5, ks = (k >> 3) & 3;
    return (((kc * ngTot + (n >> 3)) * 4 + ks) * 32 + (n & 7) * 4 + (k & 3)) * 2
         + ((k >> 2) & 1);
}
// fp16 m16n8k16 A fragment, 16-row tile, compact: u32 slot for (m, k even)
__device__ __forceinline__ int az16(int m, int k) {
    return (k >> 4) * 128 + (m & 7) * 16 + ((k & 7) >> 1) * 4
         + ((m >> 3) & 1) + 2 * ((k >> 3) & 1);
}
// fp16 m16n8k16 B fragment: u16 index for (n, k)
__device__ __forceinline__ int whidx(int n, int k, int ngTot) {
    int pair = ((k >> 4) * ngTot + (n >> 3)) * 32 + (n & 7) * 4 + ((k & 7) >> 1);
    return pair * 4 + ((k >> 3) & 1) * 2 + (k & 1);
}

// ---------------- weight prep ----------------
__global__ void prep_stack(const float* __restrict__ Wq, const float* __restrict__ bq,
                           const float* __restrict__ Wc,
                           const float* __restrict__ Wk, const float* __restrict__ bk,
                           const float* __restrict__ Wv, const float* __restrict__ bv)
{
    int r = blockIdx.x, which = blockIdx.y, l = blockIdx.z, t = threadIdx.x;
    if (which == 0) {
        if (r < 256) {
            g_Wkv[((size_t)l*512 + r)*256 + t] = Wk[((size_t)l*256 + r)*256 + t];
            if (t == 0) g_bkv[l*512 + r] = bk[l*256 + r];
        } else {
            g_Wkv[((size_t)l*512 + r)*256 + t] = Wv[((size_t)l*256 + r-256)*256 + t];
            if (t == 0) g_bkv[l*512 + r] = bv[l*256 + r-256];
        }
    } else {
        if (r < 256) {
            g_Wqc[((size_t)l*512 + r)*256 + t] = Wq[((size_t)l*256 + r)*256 + t];
            if (t == 0) g_bqc[l*512 + r] = bq[l*256 + r];
        } else {
            g_Wqc[((size_t)l*512 + r)*256 + t] = Wc[((size_t)l*256 + (r-256))*512 + t];
            if (t == 0) g_bqc[l*512 + r] = 0.f;
        }
    }
}
__global__ void prep_fold(const float* __restrict__ Wc, const float* __restrict__ Wo)
{
    int l = blockIdx.z;
    int o = blockIdx.y * 16 + threadIdx.y;
    int i = blockIdx.x * 16 + threadIdx.x;
    const float* wc2 = Wc + ((size_t)l*256 + o)*512 + 256;
    float acc = 0.f;
    for (int j = 0; j < 256; j++)
        acc += wc2[j] * Wo[((size_t)l*256 + j)*256 + i];
    g_W2[((size_t)l*256 + o)*256 + i] = acc;
}
__global__ void prep_b2(const float* __restrict__ Wc, const float* __restrict__ bo,
                        const float* __restrict__ bc)
{
    int l = blockIdx.x, o = threadIdx.x;
    const float* wc2 = Wc + ((size_t)l*256 + o)*512 + 256;
    float acc = bc[l*256 + o];
    for (int j = 0; j < 256; j++)
        acc += wc2[j] * bo[l*256 + j];
    g_b2[l*256 + o] = acc;
}
// permute a [N,256] fp32 row-major weight into tf32 fragment order
__global__ void permW(const float* __restrict__ src, uint32_t* __restrict__ dst,
                      int N, int ngTot, int srcStride, int dstStride)
{
    int l = blockIdx.y;
    int idx = blockIdx.x * 256 + threadIdx.x;
    if (idx >= N * 256) return;
    int n = idx >> 8, k = idx & 255;
    dst[(size_t)l * dstStride + bidx(n, k, ngTot)] =
        cvt_tf32(src[(size_t)l * srcStride + (size_t)n * 256 + k]);
}
// permute a [N,256] fp32 row-major weight into fp16 m16n8k16 fragment order
__global__ void permWh(const float* __restrict__ src, __half* __restrict__ dst,
                       int N, int ngTot, int srcStride, int dstStride)
{
    int l = blockIdx.y;
    int idx = blockIdx.x * 256 + threadIdx.x;
    if (idx >= N * 256) return;
    int n = idx >> 8, k = idx & 255;
    dst[(size_t)l * dstStride + whidx(n, k, ngTot)] =
        __float2half(src[(size_t)l * srcStride + (size_t)n * 256 + k]);
}
// permute activations [M,256] fp32 into tf32 fragment order
__global__ void permX(const float* __restrict__ src, uint32_t* __restrict__ dst, int mgTot)
{
    int idx = blockIdx.x * 256 + threadIdx.x;
    int row = idx >> 8, k = idx & 255;
    dst[pidx(row, k, mgTot)] = cvt_tf32(src[(size_t)row * 256 + k]);
}

// =====================================================================
// tf32 GEMM on pre-permuted operands: C[M,N] = A @ B^T + bias
// BM=128, BN=64, 256 thr. Optional fp32 C, fp16 C16, permuted-A outputs.
// =====================================================================
__global__ __launch_bounds__(256)
void gemm_perm(const uint32_t* __restrict__ Ap, int mgTot,
               const uint32_t* __restrict__ Bp, int ngTot,
               const float* __restrict__ bias,
               float* __restrict__ C, int ldc,
               uint32_t* __restrict__ P0, uint32_t* __restrict__ P1,
               __half* __restrict__ C16)
{
    __shared__ uint32_t As[2][4096];
    __shared__ uint32_t Bs[2][2048];
    const int t = threadIdx.x, lane = t & 31, warp = t >> 5;
    const int warpN = warp & 1, warpM = warp >> 1;
    const int gid = lane >> 2, tig = lane & 3;
    const int bm = blockIdx.y * 128, bn = blockIdx.x * 64;
    const int mg0 = bm >> 4, ng0 = bn >> 3;

    float acc[2][4][4];
    #pragma unroll
    for (int i = 0; i < 2; i++)
        #pragma unroll
        for (int j = 0; j < 4; j++)
            #pragma unroll
            for (int q = 0; q < 4; q++) acc[i][j][q] = 0.f;

    uint4 aR[4], bR[2];
    auto loadG = [&](int kc) {
        #pragma unroll
        for (int i = 0; i < 4; i++) {
            int idx = t + i * 256;
            int mgl = idx >> 7, r = idx & 127;
            aR[i] = ((const uint4*)Ap)[(size_t)(kc * mgTot + mg0 + mgl) * 128 + r];
        }
        #pragma unroll
        for (int i = 0; i < 2; i++) {
            int idx = t + i * 256;
            int ngl = idx >> 6, r = idx & 63;
            bR[i] = ((const uint4*)Bp)[(size_t)(kc * ngTot + ng0 + ngl) * 64 + r];
        }
    };
    auto storeS = [&](int buf) {
        #pragma unroll
        for (int i = 0; i < 4; i++) ((uint4*)As[buf])[t + i * 256] = aR[i];
        #pragma unroll
        for (int i = 0; i < 2; i++) ((uint4*)Bs[buf])[t + i * 256] = bR[i];
    };
    auto compute = [&](int buf) {
        #pragma unroll
        for (int ks = 0; ks < 4; ks++) {
            uint4 a[2]; uint2 b[4];
            #pragma unroll
            for (int mf = 0; mf < 2; mf++)
                a[mf] = ((const uint4*)As[buf])[((warpM * 2 + mf) * 4 + ks) * 32 + lane];
            #pragma unroll
            for (int nf = 0; nf < 4; nf++)
                b[nf] = ((const uint2*)Bs[buf])[((warpN * 4 + nf) * 4 + ks) * 32 + lane];
            #pragma unroll
            for (int mf = 0; mf < 2; mf++)
                #pragma unroll
                for (int nf = 0; nf < 4; nf++)
                    mma_tf32(acc[mf][nf], a[mf], b[nf]);
        }
    };

    loadG(0); storeS(0); __syncthreads();
    #pragma unroll 1
    for (int kc = 0; kc < 8; kc++) {
        int cur = kc & 1;
        if (kc < 7) loadG(kc + 1);
        compute(cur);
        if (kc < 7) { storeS(1 - cur); __syncthreads(); }
    }

    #pragma unroll
    for (int mf = 0; mf < 2; mf++) {
        int r0 = bm + warpM * 32 + mf * 16 + gid;
        #pragma unroll
        for (int nf = 0; nf < 4; nf++) {
            int c0 = bn + warpN * 32 + nf * 8 + tig * 2;
            float bx = bias ? bias[c0] : 0.f, by = bias ? bias[c0 + 1] : 0.f;
            float v00 = acc[mf][nf][0] + bx, v01 = acc[mf][nf][1] + by;
            float v10 = acc[mf][nf][2] + bx, v11 = acc[mf][nf][3] + by;
            if (C) {
                *(float2*)(C + (size_t)r0 * ldc + c0)       = make_float2(v00, v01);
                *(float2*)(C + (size_t)(r0 + 8) * ldc + c0) = make_float2(v10, v11);
            }
            if (C16) {
                ((uint32_t*)C16)[((size_t)r0 * ldc + c0) >> 1]       = f2h2(v00, v01);
                ((uint32_t*)C16)[((size_t)(r0 + 8) * ldc + c0) >> 1] = f2h2(v10, v11);
            }
            if (P0) {
                uint32_t* P = (r0 < 4096) ? P0 : P1;
                int rr   = (r0 < 4096) ? r0 : r0 - 4096;
                int mgT  = (r0 < 4096) ? 256 : 3840;
                int base = pidx(rr, c0, mgT);
                P[base]     = cvt_tf32(v00);
                P[base + 4] = cvt_tf32(v01);
                P[base + 1] = cvt_tf32(v10);
                P[base + 5] = cvt_tf32(v11);
            }
        }
    }
}

// =====================================================================
// Fused per-level kernel (fp16, 16 nodes/block — proven geometry):
// attention + zGEMM(+Zq,LN,GELU) + KV projection. 256 blocks x 256 thr.
// =====================================================================
__global__ __launch_bounds__(256)
void fused_level(const int* __restrict__ preds,     // + lv*4096*16
                 int lvbase,                         // lv*4096
                 const __half* __restrict__ KVsrc,
                 __half* __restrict__ KVdst,
                 const float* __restrict__ QZrow,    // g_QZ + lv*4096*512
                 const uint32_t* __restrict__ W2h,   // fp16 frag, layer slice
                 const float* __restrict__ b2,
                 const uint32_t* __restrict__ Wkvh,  // fp16 frag, layer slice
                 const float* __restrict__ bkv,
                 const float* __restrict__ gma, const float* __restrict__ bta,
                 float* __restrict__ outp,           // + (lv+1)*4096*1024 + (l+1)*256
                 uint32_t* __restrict__ Hp)          // g_Hp (tf32 frag) or null
{
    __shared__ int   sp[16][16];
    __shared__ float qs[16][256];
    __shared__ float sattn[16][68];
    __shared__ float redA[16][8], redB[16][8];
    extern __shared__ uint32_t Az[];                 // 2048 u32 = 8KB (fp16 frags, 16x256)

    const int t = threadIdx.x, lane = t & 31, warp = t >> 5;
    const int gid = lane >> 2, tig = lane & 3;
    const int m0 = blockIdx.x * 16;

    // ---- load preds + q rows ----
    sp[t >> 4][t & 15] = preds[m0 * 16 + t] - lvbase;
    for (int i = t; i < 1024; i += 256) {
        int m = i >> 6, c4 = i & 63;
        ((float4*)qs[m])[c4] = *(const float4*)(QZrow + (size_t)(m0 + m) * 512 + c4 * 4);
    }
    __syncthreads();

    // ---- phase A: attention (warp per node, 2 nodes/warp) ----
    const int p = lane >> 1, half = lane & 1;
    const int hlo = lane >> 4, hhi = 2 + hlo;
    for (int it = 0; it < 2; it++) {
        int m = warp + it * 8;
        const uint4* kv16 = (const uint4*)(KVsrc + (size_t)sp[m][p] * 512 + half * 128);
        const float4* q4 = (const float4*)&qs[m][half * 128];
        float s0 = 0.f, s1 = 0.f;
        #pragma unroll
        for (int j = 0; j < 8; j++) {
            uint4 kk = kv16[j];
            float4 qa = q4[j*2], qb = q4[j*2 + 1];
            float2 f0 = __half22float2(*(__half2*)&kk.x);
            float2 f1 = __half22float2(*(__half2*)&kk.y);
            float2 f2 = __half22float2(*(__half2*)&kk.z);
            float2 f3 = __half22float2(*(__half2*)&kk.w);
            s0 += f0.x*qa.x + f0.y*qa.y + f1.x*qa.z + f1.y*qa.w
                + f2.x*qb.x + f2.y*qb.y + f3.x*qb.z + f3.y*qb.w;
        }
        #pragma unroll
        for (int j = 8; j < 16; j++) {
            uint4 kk = kv16[j];
            float4 qa = q4[j*2], qb = q4[j*2 + 1];
            float2 f0 = __half22float2(*(__half2*)&kk.x);
            float2 f1 = __half22float2(*(__half2*)&kk.y);
            float2 f2 = __half22float2(*(__half2*)&kk.z);
            float2 f3 = __half22float2(*(__half2*)&kk.w);
            s1 += f0.x*qa.x + f0.y*qa.y + f1.x*qa.z + f1.y*qa.w
                + f2.x*qb.x + f2.y*qb.y + f3.x*qb.z + f3.y*qb.w;
        }
        s0 *= 0.125f; s1 *= 0.125f;
        float m0x = s0, m1x = s1;
        #pragma unroll
        for (int o = 2; o <= 16; o <<= 1) {
            m0x = fmaxf(m0x, __shfl_xor_sync(0xffffffffu, m0x, o));
            m1x = fmaxf(m1x, __shfl_xor_sync(0xffffffffu, m1x, o));
        }
        float e0 = expf(s0 - m0x), e1 = expf(s1 - m1x);
        float t0 = e0, t1 = e1;
        #pragma unroll
        for (int o = 2; o <= 16; o <<= 1) {
            t0 += __shfl_xor_sync(0xffffffffu, t0, o);
            t1 += __shfl_xor_sync(0xffffffffu, t1, o);
        }
        sattn[m][(2*half)*16 + p]   = e0 / t0;
        sattn[m][(2*half+1)*16 + p] = e1 / t1;
        __syncwarp();

        // V aggregation: lane owns elems [lane*4,+4) and [128+lane*4,+4)
        float4 alo = make_float4(0.f, 0.f, 0.f, 0.f);
        float4 ahi = make_float4(0.f, 0.f, 0.f, 0.f);
        #pragma unroll
        for (int pp = 0; pp < 16; pp++) {
            const __half* vr = KVsrc + (size_t)sp[m][pp] * 512 + 256;
            float wl = sattn[m][hlo*16 + pp], wh = sattn[m][hhi*16 + pp];
            uint2 v0 = *(const uint2*)(vr + lane * 4);
            uint2 v1 = *(const uint2*)(vr + 128 + lane * 4);
            float2 a0 = __half22float2(*(__half2*)&v0.x);
            float2 a1 = __half22float2(*(__half2*)&v0.y);
            float2 b0 = __half22float2(*(__half2*)&v1.x);
            float2 b1 = __half22float2(*(__half2*)&v1.y);
            alo.x = fmaf(wl, a0.x, alo.x); alo.y = fmaf(wl, a0.y, alo.y);
            alo.z = fmaf(wl, a1.x, alo.z); alo.w = fmaf(wl, a1.y, alo.w);
            ahi.x = fmaf(wh, b0.x, ahi.x); ahi.y = fmaf(wh, b0.y, ahi.y);
            ahi.z = fmaf(wh, b1.x, ahi.z); ahi.w = fmaf(wh, b1.y, ahi.w);
        }
        int b0s = az16(m, lane * 4);
        Az[b0s]     = f2h2(alo.x, alo.y);
        Az[b0s + 4] = f2h2(alo.z, alo.w);
        int b1s = az16(m, 128 + lane * 4);
        Az[b1s]     = f2h2(ahi.x, ahi.y);
        Az[b1s + 4] = f2h2(ahi.z, ahi.w);
    }
    __syncthreads();

    // ---- phase B: zGEMM fp16 (warp tile 16x32, 16 k-chunks) ----
    float accz[4][4];
    #pragma unroll
    for (int j = 0; j < 4; j++)
        #pragma unroll
        for (int q = 0; q < 4; q++) accz[j][q] = 0.f;

    const uint4* Az4 = (const uint4*)Az;
    #pragma unroll 1
    for (int kc = 0; kc < 16; kc++) {
        uint2 bfr[4];
        #pragma unroll
        for (int nf = 0; nf < 4; nf++)
            bfr[nf] = ((const uint2*)W2h)[(kc*32 + warp*4 + nf)*32 + lane];
        uint4 a = Az4[kc*32 + lane];
        #pragma unroll
        for (int nf = 0; nf < 4; nf++)
            mma_f16(accz[nf], a, bfr[nf]);
    }

    // ---- epilogue: +b2+Zq, LN, GELU; write out, Az (fp16), Hp (tf32) ----
    #pragma unroll
    for (int nf = 0; nf < 4; nf++) {
        int col = warp * 32 + nf * 8 + tig * 2;
        float b0 = b2[col], b1 = b2[col + 1];
        float2 zl = *(const float2*)(QZrow + (size_t)(m0 + gid) * 512 + 256 + col);
        float2 zh = *(const float2*)(QZrow + (size_t)(m0 + gid + 8) * 512 + 256 + col);
        accz[nf][0] += b0 + zl.x;
        accz[nf][1] += b1 + zl.y;
        accz[nf][2] += b0 + zh.x;
        accz[nf][3] += b1 + zh.y;
    }
    #pragma unroll
    for (int rh = 0; rh < 2; rh++) {
        float s1 = 0.f, s2 = 0.f;
        #pragma unroll
        for (int nf = 0; nf < 4; nf++) {
            float z0 = accz[nf][2*rh], z1 = accz[nf][2*rh + 1];
            s1 += z0 + z1;
            s2 += z0*z0 + z1*z1;
        }
        s1 += __shfl_xor_sync(0xffffffffu, s1, 1);
        s2 += __shfl_xor_sync(0xffffffffu, s2, 1);
        s1 += __shfl_xor_sync(0xffffffffu, s1, 2);
        s2 += __shfl_xor_sync(0xffffffffu, s2, 2);
        if (tig == 0) {
            redA[rh * 8 + gid][warp] = s1;
            redB[rh * 8 + gid][warp] = s2;
        }
    }
    __syncthreads();   // also guarantees all warps finished reading Az
    #pragma unroll
    for (int rh = 0; rh < 2; rh++) {
        int rowL = rh * 8 + gid;
        float a = 0.f, b = 0.f;
        #pragma unroll
        for (int w = 0; w < 8; w++) { a += redA[rowL][w]; b += redB[rowL][w]; }
        float mu   = a * (1.f / 256.f);
        float var  = b * (1.f / 256.f) - mu * mu;
        float rstd = rsqrtf(var + LN_EPS);
        #pragma unroll
        for (int nf = 0; nf < 4; nf++) {
            int col = warp * 32 + nf * 8 + tig * 2;
            float z0 = (accz[nf][2*rh]     - mu) * rstd * gma[col]     + bta[col];
            float z1 = (accz[nf][2*rh + 1] - mu) * rstd * gma[col + 1] + bta[col + 1];
            float g0 = 0.5f * z0 * (1.f + erff(z0 * 0.70710678118654752f));
            float g1 = 0.5f * z1 * (1.f + erff(z1 * 0.70710678118654752f));
            ((float2*)(outp + (size_t)(m0 + rowL) * 1024))[col >> 1] =
                make_float2(g0, g1);
            Az[az16(rowL, col)] = f2h2(g0, g1);
            if (Hp) {
                int gb = pidx(lvbase + m0 + rowL, col, 3840);
                Hp[gb] = cvt_tf32(g0); Hp[gb + 4] = cvt_tf32(g1);
            }
        }
    }
    __syncthreads();

    // ---- phase C: KV projection fp16 (warp tile 16x64, 16 k-chunks) ----
    float acck[8][4];
    #pragma unroll
    for (int j = 0; j < 8; j++)
        #pragma unroll
        for (int q = 0; q < 4; q++) acck[j][q] = 0.f;

    #pragma unroll 1
    for (int kc = 0; kc < 16; kc++) {
        uint2 bk[8];
        #pragma unroll
        for (int nf = 0; nf < 8; nf++)
            bk[nf] = ((const uint2*)Wkvh)[(kc*64 + warp*8 + nf)*32 + lane];
        uint4 a = Az4[kc*32 + lane];
        #pragma unroll
        for (int nf = 0; nf < 8; nf++)
            mma_f16(acck[nf], a, bk[nf]);
    }
    {
        uint32_t* KVd = (uint32_t*)KVdst;
        int r0 = m0 + gid;
        #pragma unroll
        for (int nf = 0; nf < 8; nf++) {
            int col = warp * 64 + nf * 8 + tig * 2;
            float b0 = bkv[col], b1 = bkv[col + 1];
            KVd[(size_t)r0 * 256 + (col >> 1)] =
                f2h2(acck[nf][0] + b0, acck[nf][1] + b1);
            KVd[(size_t)(r0 + 8) * 256 + (col >> 1)] =
                f2h2(acck[nf][2] + b0, acck[nf][3] + b1);
        }
    }
}

// ---------------- final level-0 copies ----------------
__global__ __launch_bounds__(256)
void copy0(float* __restrict__ out)
{
    int idx = blockIdx.x * 256 + threadIdx.x;   // 4096*256
    int n = idx >> 8, c = idx & 255;
    float v = out[(size_t)n * 1024 + c];
    out[(size_t)n * 1024 + 256 + c] = v;
    out[(size_t)n * 1024 + 512 + c] = v;
    out[(size_t)n * 1024 + 768 + c] = v;
}

// ---------------- host driver ----------------
extern "C" void kernel_launch(void* const* d_in, const int* in_sizes, int n_in,
                              void* d_out, int out_size)
{
    const float* x        = (const float*)d_in[0];
    const int*   preds_lv = (const int*)d_in[3];
    const float* W_in = (const float*)d_in[4];
    const float* b_in = (const float*)d_in[5];
    const float* Wq   = (const float*)d_in[6];
    const float* bq   = (const float*)d_in[7];
    const float* Wk   = (const float*)d_in[8];
    const float* bk   = (const float*)d_in[9];
    const float* Wv   = (const float*)d_in[10];
    const float* bv   = (const float*)d_in[11];
    const float* Wo   = (const float*)d_in[12];
    const float* bo   = (const float*)d_in[13];
    const float* Wc   = (const float*)d_in[14];
    const float* bc   = (const float*)d_in[15];
    const float* ln_g = (const float*)d_in[16];
    const float* ln_b = (const float*)d_in[17];
    float* out = (float*)d_out;

    float *pQZ, *pWkv, *pbkv, *pWqc, *pbqc, *pW2, *pb2;
    __half *pKV16, *pW2h, *pWkvh;
    uint32_t *pXp, *pHp, *pHp0, *pWkvp, *pWqcp, *pWinp;
    cudaGetSymbolAddress((void**)&pQZ,   g_QZ);
    cudaGetSymbolAddress((void**)&pKV16, g_KV16);
    cudaGetSymbolAddress((void**)&pWkv,  g_Wkv);
    cudaGetSymbolAddress((void**)&pbkv,  g_bkv);
    cudaGetSymbolAddress((void**)&pWqc,  g_Wqc);
    cudaGetSymbolAddress((void**)&pbqc,  g_bqc);
    cudaGetSymbolAddress((void**)&pW2,   g_W2);
    cudaGetSymbolAddress((void**)&pb2,   g_b2);
    cudaGetSymbolAddress((void**)&pXp,   g_Xp);
    cudaGetSymbolAddress((void**)&pHp,   g_Hp);
    cudaGetSymbolAddress((void**)&pHp0,  g_Hp0);
    cudaGetSymbolAddress((void**)&pWkvp, g_Wkvp);
    cudaGetSymbolAddress((void**)&pWqcp, g_Wqcp);
    cudaGetSymbolAddress((void**)&pWinp, g_Winp);
    cudaGetSymbolAddress((void**)&pW2h,  g_W2h);
    cudaGetSymbolAddress((void**)&pWkvh, g_Wkvh);

    // weight prep + permutes
    prep_stack<<<dim3(512, 2, LAYERS), 256>>>(Wq, bq, Wc, Wk, bk, Wv, bv);
    prep_fold<<<dim3(16, 16, LAYERS), dim3(16, 16)>>>(Wc, Wo);
    prep_b2<<<LAYERS, 256>>>(Wc, bo, bc);
    permW<<<dim3(256, 1), 256>>>(W_in, pWinp, 256, 32, 0, 0);
    permW<<<dim3(512, LAYERS), 256>>>(pWqc, pWqcp, 512, 64, 512*256, 512*256);
    permW<<<dim3(512, LAYERS), 256>>>(pWkv, pWkvp, 512, 64, 512*256, 512*256);
    permWh<<<dim3(256, LAYERS), 256>>>(pW2,  pW2h,  256, 32, 256*256, 256*256);
    permWh<<<dim3(512, LAYERS), 256>>>(pWkv, pWkvh, 512, 64, 512*256, 512*256);
    permX<<<NTOT, 256>>>(x, pXp, 4096);

    // h0 = x @ W_in^T + b_in -> out[:,0:256] + permuted copies
    gemm_perm<<<dim3(4, NTOT/128), 256>>>(pXp, 4096, pWinp, 32, b_in,
                                          out, 1024, pHp0, pHp, (__half*)0);

    for (int l = 0; l < LAYERS; l++) {
        // [Qh | q@Wc1^T] for all non-source nodes from h_l (permuted in g_Hp)
        gemm_perm<<<dim3(8, NB/128), 256>>>(pHp, 3840,
                                            pWqcp + (size_t)l*512*256, 64,
                                            pbqc + l*512, pQZ, 512,
                                            (uint32_t*)0, (uint32_t*)0, (__half*)0);
        // K|V of level 0 -> fp16 ping buffer 0
        gemm_perm<<<dim3(8, MNODES/128), 256>>>(pHp0, 256,
                                                pWkvp + (size_t)l*512*256, 64,
                                                pbkv + l*512,
                                                (float*)0, 512,
                                                (uint32_t*)0, (uint32_t*)0,
                                                pKV16);
        for (int lv = 0; lv < NLEV - 1; lv++) {
            __half* KVsrc = pKV16 + (size_t)(lv & 1) * MNODES * 512;
            __half* KVdst = pKV16 + (size_t)((lv + 1) & 1) * MNODES * 512;
            fused_level<<<MNODES/16, 256, 8192>>>(
                preds_lv + (size_t)lv * MNODES * 16,
                lv * MNODES,
                KVsrc, KVdst,
                pQZ + (size_t)lv * MNODES * 512,
                (const uint32_t*)(pW2h + (size_t)l*256*256), pb2 + l*256,
                (const uint32_t*)(pWkvh + (size_t)l*512*256), pbkv + l*512,
                ln_g + l*256, ln_b + l*256,
                out + (size_t)(lv + 1) * MNODES * 1024 + (size_t)(l + 1) * 256,
                (l < LAYERS - 1) ? pHp : (uint32_t*)0);
        }
    }
    copy0<<<4096, 256>>>(out);
}

// round 15
// speedup vs baseline: 1.3397x; 1.0556x over previous
#include <cuda_runtime.h>
#include <cuda_fp16.h>
#include <math.h>
#include <stdint.h>

#define MNODES 4096
#define NLEV   16
#define NTOT   65536
#define HID    256
#define PRED   16
#define HEADS  4
#define HD     64
#define LAYERS 3
#define NB     61440
#define LN_EPS 1e-5f

// ---------------- device scratch ----------------
__device__ __align__(16) float    g_QZ[(size_t)NB * 512];          // [Qh | q@Wc1^T] fp32
__device__ __align__(16) __half   g_KV16[2][(size_t)MNODES * 512]; // ping-pong [K|V] fp16
__device__ __align__(16) uint32_t g_Xp16[(size_t)NTOT * 128];      // x, fp16 A-frags (mg 4096)
__device__ __align__(16) uint32_t g_Hp16[(size_t)NB * 128];        // h rows 4096.., fp16 A-frags (mg 3840)
__device__ __align__(16) uint32_t g_Hp016[(size_t)MNODES * 128];   // h level-0 rows, fp16 A-frags (mg 256)
__device__ __align__(16) float    g_Wkv[LAYERS * 512 * 256];       // stacked fp32 (staging)
__device__ __align__(16) float    g_bkv[LAYERS * 512];
__device__ __align__(16) float    g_Wqc[LAYERS * 512 * 256];
__device__ __align__(16) float    g_bqc[LAYERS * 512];
__device__ __align__(16) float    g_W2 [LAYERS * 256 * 256];
__device__ __align__(16) float    g_b2 [LAYERS * 256];
__device__ __align__(16) __half   g_Winh[256 * 256];               // fp16 B-frags
__device__ __align__(16) __half   g_Wqch[LAYERS * 512 * 256];
__device__ __align__(16) __half   g_W2h [LAYERS * 256 * 256];
__device__ __align__(16) __half   g_Wkvh[LAYERS * 512 * 256];

// ---------------- helpers ----------------
__device__ __forceinline__ void mma_f16(float c[4], const uint4& a, const uint2& b) {
    asm volatile(
        "mma.sync.aligned.m16n8k16.row.col.f32.f16.f16.f32 "
        "{%0,%1,%2,%3}, {%4,%5,%6,%7}, {%8,%9}, {%0,%1,%2,%3};"
        : "+f"(c[0]), "+f"(c[1]), "+f"(c[2]), "+f"(c[3])
        : "r"(a.x), "r"(a.y), "r"(a.z), "r"(a.w), "r"(b.x), "r"(b.y));
}
__device__ __forceinline__ uint32_t f2h2(float a, float b) {
    __half2 h = __floats2half2_rn(a, b); return *(uint32_t*)&h;
}
// fp16 m16n8k16 A fragment: u32 slot for (row, k even); mgTot row-groups of 16
__device__ __forceinline__ int pidx16(int row, int k, int mgTot) {
    return ((k >> 4) * mgTot + (row >> 4)) * 128 + (row & 7) * 16
         + ((k & 7) >> 1) * 4 + ((row >> 3) & 1) + 2 * ((k >> 3) & 1);
}
// 16-row tile special case (fused kernel smem)
__device__ __forceinline__ int az16(int m, int k) { return pidx16(m, k, 1); }
// fp16 m16n8k16 B fragment: u16 index for (n, k)
__device__ __forceinline__ int whidx(int n, int k, int ngTot) {
    int pair = ((k >> 4) * ngTot + (n >> 3)) * 32 + (n & 7) * 4 + ((k & 7) >> 1);
    return pair * 4 + ((k >> 3) & 1) * 2 + (k & 1);
}

// ---------------- weight prep ----------------
__global__ void prep_stack(const float* __restrict__ Wq, const float* __restrict__ bq,
                           const float* __restrict__ Wc,
                           const float* __restrict__ Wk, const float* __restrict__ bk,
                           const float* __restrict__ Wv, const float* __restrict__ bv)
{
    int r = blockIdx.x, which = blockIdx.y, l = blockIdx.z, t = threadIdx.x;
    if (which == 0) {
        if (r < 256) {
            g_Wkv[((size_t)l*512 + r)*256 + t] = Wk[((size_t)l*256 + r)*256 + t];
            if (t == 0) g_bkv[l*512 + r] = bk[l*256 + r];
        } else {
            g_Wkv[((size_t)l*512 + r)*256 + t] = Wv[((size_t)l*256 + r-256)*256 + t];
            if (t == 0) g_bkv[l*512 + r] = bv[l*256 + r-256];
        }
    } else {
        if (r < 256) {
            g_Wqc[((size_t)l*512 + r)*256 + t] = Wq[((size_t)l*256 + r)*256 + t];
            if (t == 0) g_bqc[l*512 + r] = bq[l*256 + r];
        } else {
            g_Wqc[((size_t)l*512 + r)*256 + t] = Wc[((size_t)l*256 + (r-256))*512 + t];
            if (t == 0) g_bqc[l*512 + r] = 0.f;
        }
    }
}
__global__ void prep_fold(const float* __restrict__ Wc, const float* __restrict__ Wo)
{
    int l = blockIdx.z;
    int o = blockIdx.y * 16 + threadIdx.y;
    int i = blockIdx.x * 16 + threadIdx.x;
    const float* wc2 = Wc + ((size_t)l*256 + o)*512 + 256;
    float acc = 0.f;
    for (int j = 0; j < 256; j++)
        acc += wc2[j] * Wo[((size_t)l*256 + j)*256 + i];
    g_W2[((size_t)l*256 + o)*256 + i] = acc;
}
__global__ void prep_b2(const float* __restrict__ Wc, const float* __restrict__ bo,
                        const float* __restrict__ bc)
{
    int l = blockIdx.x, o = threadIdx.x;
    const float* wc2 = Wc + ((size_t)l*256 + o)*512 + 256;
    float acc = bc[l*256 + o];
    for (int j = 0; j < 256; j++)
        acc += wc2[j] * bo[l*256 + j];
    g_b2[l*256 + o] = acc;
}
// permute a [N,256] fp32 row-major weight into fp16 m16n8k16 B-fragment order
__global__ void permWh(const float* __restrict__ src, __half* __restrict__ dst,
                       int N, int ngTot, int srcStride, int dstStride)
{
    int l = blockIdx.y;
    int idx = blockIdx.x * 256 + threadIdx.x;
    if (idx >= N * 256) return;
    int n = idx >> 8, k = idx & 255;
    dst[(size_t)l * dstStride + whidx(n, k, ngTot)] =
        __float2half(src[(size_t)l * srcStride + (size_t)n * 256 + k]);
}
// permute activations [M,256] fp32 into fp16 A-fragment order (pair per thread)
__global__ void permXh(const float* __restrict__ src, uint32_t* __restrict__ dst, int mgTot)
{
    int idx = blockIdx.x * 256 + threadIdx.x;   // row*128 + kpair
    int row = idx >> 7, kp = idx & 127;
    const float* s = src + (size_t)row * 256 + kp * 2;
    dst[pidx16(row, kp * 2, mgTot)] = f2h2(s[0], s[1]);
}

// =====================================================================
// fp16 GEMM on pre-permuted operands: C[M,N] = A @ B^T + bias
// BM=128, BN=64, 256 thr (8 warps, 4M x 2N), 16 k-chunks of 16.
// Optional fp32 C, fp16 row-major C16, fp16-frag P0/P1 outputs.
// =====================================================================
__global__ __launch_bounds__(256)
void gemm16(const uint32_t* __restrict__ Ap, int mgTot,
            const uint32_t* __restrict__ Bp, int ngTot,
            const float* __restrict__ bias,
            float* __restrict__ C, int ldc,
            uint32_t* __restrict__ P0, uint32_t* __restrict__ P1,
            __half* __restrict__ C16)
{
    __shared__ uint32_t As[2][1024];
    __shared__ uint32_t Bs[2][512];
    const int t = threadIdx.x, lane = t & 31, warp = t >> 5;
    const int warpN = warp & 1, warpM = warp >> 1;
    const int gid = lane >> 2, tig = lane & 3;
    const int bm = blockIdx.y * 128, bn = blockIdx.x * 64;
    const int mg0 = bm >> 4, ng0 = bn >> 3;

    float acc[2][4][4];
    #pragma unroll
    for (int i = 0; i < 2; i++)
        #pragma unroll
        for (int j = 0; j < 4; j++)
            #pragma unroll
            for (int q = 0; q < 4; q++) acc[i][j][q] = 0.f;

    uint4 aR; uint2 bR;
    auto loadG = [&](int kc) {
        aR = ((const uint4*)Ap)[(size_t)(kc * mgTot + mg0) * 32 + t];
        bR = ((const uint2*)Bp)[(size_t)(kc * ngTot + ng0) * 32 + t];
    };
    auto storeS = [&](int buf) {
        ((uint4*)As[buf])[t] = aR;
        ((uint2*)Bs[buf])[t] = bR;
    };
    auto compute = [&](int buf) {
        uint4 a[2]; uint2 b[4];
        #pragma unroll
        for (int mf = 0; mf < 2; mf++)
            a[mf] = ((const uint4*)As[buf])[(warpM * 2 + mf) * 32 + lane];
        #pragma unroll
        for (int nf = 0; nf < 4; nf++)
            b[nf] = ((const uint2*)Bs[buf])[(warpN * 4 + nf) * 32 + lane];
        #pragma unroll
        for (int mf = 0; mf < 2; mf++)
            #pragma unroll
            for (int nf = 0; nf < 4; nf++)
                mma_f16(acc[mf][nf], a[mf], b[nf]);
    };

    loadG(0); storeS(0); __syncthreads();
    #pragma unroll 1
    for (int kc = 0; kc < 16; kc++) {
        int cur = kc & 1;
        if (kc < 15) loadG(kc + 1);
        compute(cur);
        if (kc < 15) { storeS(1 - cur); __syncthreads(); }
    }

    #pragma unroll
    for (int mf = 0; mf < 2; mf++) {
        int r0 = bm + warpM * 32 + mf * 16 + gid;
        #pragma unroll
        for (int nf = 0; nf < 4; nf++) {
            int c0 = bn + warpN * 32 + nf * 8 + tig * 2;
            float bx = bias ? bias[c0] : 0.f, by = bias ? bias[c0 + 1] : 0.f;
            float v00 = acc[mf][nf][0] + bx, v01 = acc[mf][nf][1] + by;
            float v10 = acc[mf][nf][2] + bx, v11 = acc[mf][nf][3] + by;
            if (C) {
                *(float2*)(C + (size_t)r0 * ldc + c0)       = make_float2(v00, v01);
                *(float2*)(C + (size_t)(r0 + 8) * ldc + c0) = make_float2(v10, v11);
            }
            if (C16) {
                ((uint32_t*)C16)[((size_t)r0 * ldc + c0) >> 1]       = f2h2(v00, v01);
                ((uint32_t*)C16)[((size_t)(r0 + 8) * ldc + c0) >> 1] = f2h2(v10, v11);
            }
            if (P0) {
                uint32_t* P = (r0 < 4096) ? P0 : P1;
                int rr   = (r0 < 4096) ? r0 : r0 - 4096;
                int mgT  = (r0 < 4096) ? 256 : 3840;
                int base = pidx16(rr, c0, mgT);
                P[base]     = f2h2(v00, v01);
                P[base + 1] = f2h2(v10, v11);
            }
        }
    }
}

// =====================================================================
// Fused per-level kernel (fp16, 16 nodes/block — proven geometry):
// attention + zGEMM(+Zq,LN,GELU) + KV projection. 256 blocks x 256 thr.
// =====================================================================
__global__ __launch_bounds__(256)
void fused_level(const int* __restrict__ preds,     // + lv*4096*16
                 int lvbase,                         // lv*4096
                 const __half* __restrict__ KVsrc,
                 __half* __restrict__ KVdst,
                 const float* __restrict__ QZrow,    // g_QZ + lv*4096*512
                 const uint32_t* __restrict__ W2h,   // fp16 frag, layer slice
                 const float* __restrict__ b2,
                 const uint32_t* __restrict__ Wkvh,  // fp16 frag, layer slice
                 const float* __restrict__ bkv,
                 const float* __restrict__ gma, const float* __restrict__ bta,
                 float* __restrict__ outp,           // + (lv+1)*4096*1024 + (l+1)*256
                 uint32_t* __restrict__ Hp)          // g_Hp16 (fp16 frag) or null
{
    __shared__ int   sp[16][16];
    __shared__ float qs[16][256];
    __shared__ float sattn[16][68];
    __shared__ float redA[16][8], redB[16][8];
    extern __shared__ uint32_t Az[];                 // 2048 u32 = 8KB (fp16 frags, 16x256)

    const int t = threadIdx.x, lane = t & 31, warp = t >> 5;
    const int gid = lane >> 2, tig = lane & 3;
    const int m0 = blockIdx.x * 16;

    // ---- load preds + q rows ----
    sp[t >> 4][t & 15] = preds[m0 * 16 + t] - lvbase;
    for (int i = t; i < 1024; i += 256) {
        int m = i >> 6, c4 = i & 63;
        ((float4*)qs[m])[c4] = *(const float4*)(QZrow + (size_t)(m0 + m) * 512 + c4 * 4);
    }
    __syncthreads();

    // ---- phase A: attention (warp per node, 2 nodes/warp) ----
    const int p = lane >> 1, half = lane & 1;
    const int hlo = lane >> 4, hhi = 2 + hlo;
    for (int it = 0; it < 2; it++) {
        int m = warp + it * 8;
        const uint4* kv16 = (const uint4*)(KVsrc + (size_t)sp[m][p] * 512 + half * 128);
        const float4* q4 = (const float4*)&qs[m][half * 128];
        float s0 = 0.f, s1 = 0.f;
        #pragma unroll
        for (int j = 0; j < 8; j++) {
            uint4 kk = kv16[j];
            float4 qa = q4[j*2], qb = q4[j*2 + 1];
            float2 f0 = __half22float2(*(__half2*)&kk.x);
            float2 f1 = __half22float2(*(__half2*)&kk.y);
            float2 f2 = __half22float2(*(__half2*)&kk.z);
            float2 f3 = __half22float2(*(__half2*)&kk.w);
            s0 += f0.x*qa.x + f0.y*qa.y + f1.x*qa.z + f1.y*qa.w
                + f2.x*qb.x + f2.y*qb.y + f3.x*qb.z + f3.y*qb.w;
        }
        #pragma unroll
        for (int j = 8; j < 16; j++) {
            uint4 kk = kv16[j];
            float4 qa = q4[j*2], qb = q4[j*2 + 1];
            float2 f0 = __half22float2(*(__half2*)&kk.x);
            float2 f1 = __half22float2(*(__half2*)&kk.y);
            float2 f2 = __half22float2(*(__half2*)&kk.z);
            float2 f3 = __half22float2(*(__half2*)&kk.w);
            s1 += f0.x*qa.x + f0.y*qa.y + f1.x*qa.z + f1.y*qa.w
                + f2.x*qb.x + f2.y*qb.y + f3.x*qb.z + f3.y*qb.w;
        }
        s0 *= 0.125f; s1 *= 0.125f;
        float m0x = s0, m1x = s1;
        #pragma unroll
        for (int o = 2; o <= 16; o <<= 1) {
            m0x = fmaxf(m0x, __shfl_xor_sync(0xffffffffu, m0x, o));
            m1x = fmaxf(m1x, __shfl_xor_sync(0xffffffffu, m1x, o));
        }
        float e0 = expf(s0 - m0x), e1 = expf(s1 - m1x);
        float t0 = e0, t1 = e1;
        #pragma unroll
        for (int o = 2; o <= 16; o <<= 1) {
            t0 += __shfl_xor_sync(0xffffffffu, t0, o);
            t1 += __shfl_xor_sync(0xffffffffu, t1, o);
        }
        sattn[m][(2*half)*16 + p]   = e0 / t0;
        sattn[m][(2*half+1)*16 + p] = e1 / t1;
        __syncwarp();

        // V aggregation: lane owns elems [lane*4,+4) and [128+lane*4,+4)
        float4 alo = make_float4(0.f, 0.f, 0.f, 0.f);
        float4 ahi = make_float4(0.f, 0.f, 0.f, 0.f);
        #pragma unroll
        for (int pp = 0; pp < 16; pp++) {
            const __half* vr = KVsrc + (size_t)sp[m][pp] * 512 + 256;
            float wl = sattn[m][hlo*16 + pp], wh = sattn[m][hhi*16 + pp];
            uint2 v0 = *(const uint2*)(vr + lane * 4);
            uint2 v1 = *(const uint2*)(vr + 128 + lane * 4);
            float2 a0 = __half22float2(*(__half2*)&v0.x);
            float2 a1 = __half22float2(*(__half2*)&v0.y);
            float2 b0 = __half22float2(*(__half2*)&v1.x);
            float2 b1 = __half22float2(*(__half2*)&v1.y);
            alo.x = fmaf(wl, a0.x, alo.x); alo.y = fmaf(wl, a0.y, alo.y);
            alo.z = fmaf(wl, a1.x, alo.z); alo.w = fmaf(wl, a1.y, alo.w);
            ahi.x = fmaf(wh, b0.x, ahi.x); ahi.y = fmaf(wh, b0.y, ahi.y);
            ahi.z = fmaf(wh, b1.x, ahi.z); ahi.w = fmaf(wh, b1.y, ahi.w);
        }
        int b0s = az16(m, lane * 4);
        Az[b0s]     = f2h2(alo.x, alo.y);
        Az[b0s + 4] = f2h2(alo.z, alo.w);
        int b1s = az16(m, 128 + lane * 4);
        Az[b1s]     = f2h2(ahi.x, ahi.y);
        Az[b1s + 4] = f2h2(ahi.z, ahi.w);
    }
    __syncthreads();

    // ---- phase B: zGEMM fp16 (warp tile 16x32, 16 k-chunks) ----
    float accz[4][4];
    #pragma unroll
    for (int j = 0; j < 4; j++)
        #pragma unroll
        for (int q = 0; q < 4; q++) accz[j][q] = 0.f;

    const uint4* Az4 = (const uint4*)Az;
    #pragma unroll 1
    for (int kc = 0; kc < 16; kc++) {
        uint2 bfr[4];
        #pragma unroll
        for (int nf = 0; nf < 4; nf++)
            bfr[nf] = ((const uint2*)W2h)[(kc*32 + warp*4 + nf)*32 + lane];
        uint4 a = Az4[kc*32 + lane];
        #pragma unroll
        for (int nf = 0; nf < 4; nf++)
            mma_f16(accz[nf], a, bfr[nf]);
    }

    // ---- epilogue: +b2+Zq, LN, GELU; write out, Az (fp16), Hp (fp16) ----
    #pragma unroll
    for (int nf = 0; nf < 4; nf++) {
        int col = warp * 32 + nf * 8 + tig * 2;
        float b0 = b2[col], b1 = b2[col + 1];
        float2 zl = *(const float2*)(QZrow + (size_t)(m0 + gid) * 512 + 256 + col);
        float2 zh = *(const float2*)(QZrow + (size_t)(m0 + gid + 8) * 512 + 256 + col);
        accz[nf][0] += b0 + zl.x;
        accz[nf][1] += b1 + zl.y;
        accz[nf][2] += b0 + zh.x;
        accz[nf][3] += b1 + zh.y;
    }
    #pragma unroll
    for (int rh = 0; rh < 2; rh++) {
        float s1 = 0.f, s2 = 0.f;
        #pragma unroll
        for (int nf = 0; nf < 4; nf++) {
            float z0 = accz[nf][2*rh], z1 = accz[nf][2*rh + 1];
            s1 += z0 + z1;
            s2 += z0*z0 + z1*z1;
        }
        s1 += __shfl_xor_sync(0xffffffffu, s1, 1);
        s2 += __shfl_xor_sync(0xffffffffu, s2, 1);
        s1 += __shfl_xor_sync(0xffffffffu, s1, 2);
        s2 += __shfl_xor_sync(0xffffffffu, s2, 2);
        if (tig == 0) {
            redA[rh * 8 + gid][warp] = s1;
            redB[rh * 8 + gid][warp] = s2;
        }
    }
    __syncthreads();   // also guarantees all warps finished reading Az
    #pragma unroll
    for (int rh = 0; rh < 2; rh++) {
        int rowL = rh * 8 + gid;
        float a = 0.f, b = 0.f;
        #pragma unroll
        for (int w = 0; w < 8; w++) { a += redA[rowL][w]; b += redB[rowL][w]; }
        float mu   = a * (1.f / 256.f);
        float var  = b * (1.f / 256.f) - mu * mu;
        float rstd = rsqrtf(var + LN_EPS);
        #pragma unroll
        for (int nf = 0; nf < 4; nf++) {
            int col = warp * 32 + nf * 8 + tig * 2;
            float z0 = (accz[nf][2*rh]     - mu) * rstd * gma[col]     + bta[col];
            float z1 = (accz[nf][2*rh + 1] - mu) * rstd * gma[col + 1] + bta[col + 1];
            float g0 = 0.5f * z0 * (1.f + erff(z0 * 0.70710678118654752f));
            float g1 = 0.5f * z1 * (1.f + erff(z1 * 0.70710678118654752f));
            ((float2*)(outp + (size_t)(m0 + rowL) * 1024))[col >> 1] =
                make_float2(g0, g1);
            Az[az16(rowL, col)] = f2h2(g0, g1);
            if (Hp)
                Hp[pidx16(lvbase + m0 + rowL, col, 3840)] = f2h2(g0, g1);
        }
    }
    __syncthreads();

    // ---- phase C: KV projection fp16 (warp tile 16x64, 16 k-chunks) ----
    float acck[8][4];
    #pragma unroll
    for (int j = 0; j < 8; j++)
        #pragma unroll
        for (int q = 0; q < 4; q++) acck[j][q] = 0.f;

    #pragma unroll 1
    for (int kc = 0; kc < 16; kc++) {
        uint2 bk[8];
        #pragma unroll
        for (int nf = 0; nf < 8; nf++)
            bk[nf] = ((const uint2*)Wkvh)[(kc*64 + warp*8 + nf)*32 + lane];
        uint4 a = Az4[kc*32 + lane];
        #pragma unroll
        for (int nf = 0; nf < 8; nf++)
            mma_f16(acck[nf], a, bk[nf]);
    }
    {
        uint32_t* KVd = (uint32_t*)KVdst;
        int r0 = m0 + gid;
        #pragma unroll
        for (int nf = 0; nf < 8; nf++) {
            int col = warp * 64 + nf * 8 + tig * 2;
            float b0 = bkv[col], b1 = bkv[col + 1];
            KVd[(size_t)r0 * 256 + (col >> 1)] =
                f2h2(acck[nf][0] + b0, acck[nf][1] + b1);
            KVd[(size_t)(r0 + 8) * 256 + (col >> 1)] =
                f2h2(acck[nf][2] + b0, acck[nf][3] + b1);
        }
    }
}

// ---------------- final level-0 copies ----------------
__global__ __launch_bounds__(256)
void copy0(float* __restrict__ out)
{
    int idx = blockIdx.x * 256 + threadIdx.x;   // 4096*256
    int n = idx >> 8, c = idx & 255;
    float v = out[(size_t)n * 1024 + c];
    out[(size_t)n * 1024 + 256 + c] = v;
    out[(size_t)n * 1024 + 512 + c] = v;
    out[(size_t)n * 1024 + 768 + c] = v;
}

// ---------------- host driver ----------------
extern "C" void kernel_launch(void* const* d_in, const int* in_sizes, int n_in,
                              void* d_out, int out_size)
{
    const float* x        = (const float*)d_in[0];
    const int*   preds_lv = (const int*)d_in[3];
    const float* W_in = (const float*)d_in[4];
    const float* b_in = (const float*)d_in[5];
    const float* Wq   = (const float*)d_in[6];
    const float* bq   = (const float*)d_in[7];
    const float* Wk   = (const float*)d_in[8];
    const float* bk   = (const float*)d_in[9];
    const float* Wv   = (const float*)d_in[10];
    const float* bv   = (const float*)d_in[11];
    const float* Wo   = (const float*)d_in[12];
    const float* bo   = (const float*)d_in[13];
    const float* Wc   = (const float*)d_in[14];
    const float* bc   = (const float*)d_in[15];
    const float* ln_g = (const float*)d_in[16];
    const float* ln_b = (const float*)d_in[17];
    float* out = (float*)d_out;

    float *pQZ, *pWkv, *pbkv, *pWqc, *pbqc, *pW2, *pb2;
    __half *pKV16, *pW2h, *pWkvh, *pWqch, *pWinh;
    uint32_t *pXp16, *pHp16, *pHp016;
    cudaGetSymbolAddress((void**)&pQZ,    g_QZ);
    cudaGetSymbolAddress((void**)&pKV16,  g_KV16);
    cudaGetSymbolAddress((void**)&pWkv,   g_Wkv);
    cudaGetSymbolAddress((void**)&pbkv,   g_bkv);
    cudaGetSymbolAddress((void**)&pWqc,   g_Wqc);
    cudaGetSymbolAddress((void**)&pbqc,   g_bqc);
    cudaGetSymbolAddress((void**)&pW2,    g_W2);
    cudaGetSymbolAddress((void**)&pb2,    g_b2);
    cudaGetSymbolAddress((void**)&pXp16,  g_Xp16);
    cudaGetSymbolAddress((void**)&pHp16,  g_Hp16);
    cudaGetSymbolAddress((void**)&pHp016, g_Hp016);
    cudaGetSymbolAddress((void**)&pW2h,   g_W2h);
    cudaGetSymbolAddress((void**)&pWkvh,  g_Wkvh);
    cudaGetSymbolAddress((void**)&pWqch,  g_Wqch);
    cudaGetSymbolAddress((void**)&pWinh,  g_Winh);

    // weight prep + permutes
    prep_stack<<<dim3(512, 2, LAYERS), 256>>>(Wq, bq, Wc, Wk, bk, Wv, bv);
    prep_fold<<<dim3(16, 16, LAYERS), dim3(16, 16)>>>(Wc, Wo);
    prep_b2<<<LAYERS, 256>>>(Wc, bo, bc);
    permWh<<<dim3(256, 1), 256>>>(W_in, pWinh, 256, 32, 0, 0);
    permWh<<<dim3(512, LAYERS), 256>>>(pWqc, pWqch, 512, 64, 512*256, 512*256);
    permWh<<<dim3(256, LAYERS), 256>>>(pW2,  pW2h,  256, 32, 256*256, 256*256);
    permWh<<<dim3(512, LAYERS), 256>>>(pWkv, pWkvh, 512, 64, 512*256, 512*256);
    permXh<<<NTOT/2, 256>>>(x, pXp16, 4096);

    // h0 = x @ W_in^T + b_in -> out[:,0:256] + fp16-frag copies
    gemm16<<<dim3(4, NTOT/128), 256>>>(pXp16, 4096, (const uint32_t*)pWinh, 32, b_in,
                                       out, 1024, pHp016, pHp16, (__half*)0);

    for (int l = 0; l < LAYERS; l++) {
        // [Qh | q@Wc1^T] for all non-source nodes from h_l (fp16 frags in g_Hp16)
        gemm16<<<dim3(8, NB/128), 256>>>(pHp16, 3840,
                                         (const uint32_t*)(pWqch + (size_t)l*512*256), 64,
                                         pbqc + l*512, pQZ, 512,
                                         (uint32_t*)0, (uint32_t*)0, (__half*)0);
        // K|V of level 0 -> fp16 ping buffer 0
        gemm16<<<dim3(8, MNODES/128), 256>>>(pHp016, 256,
                                             (const uint32_t*)(pWkvh + (size_t)l*512*256), 64,
                                             pbkv + l*512,
                                             (float*)0, 512,
                                             (uint32_t*)0, (uint32_t*)0,
                                             pKV16);
        for (int lv = 0; lv < NLEV - 1; lv++) {
            __half* KVsrc = pKV16 + (size_t)(lv & 1) * MNODES * 512;
            __half* KVdst = pKV16 + (size_t)((lv + 1) & 1) * MNODES * 512;
            fused_level<<<MNODES/16, 256, 8192>>>(
                preds_lv + (size_t)lv * MNODES * 16,
                lv * MNODES,
                KVsrc, KVdst,
                pQZ + (size_t)lv * MNODES * 512,
                (const uint32_t*)(pW2h + (size_t)l*256*256), pb2 + l*256,
                (const uint32_t*)(pWkvh + (size_t)l*512*256), pbkv + l*512,
                ln_g + l*256, ln_b + l*256,
                out + (size_t)(lv + 1) * MNODES * 1024 + (size_t)(l + 1) * 256,
                (l < LAYERS - 1) ? pHp16 : (uint32_t*)0);
        }
    }
    copy0<<<4096, 256>>>(out);
}